// round 16
// baseline (speedup 1.0000x reference)
#include <cuda_runtime.h>

#define N_NODES 10000
#define N_EDGES 160000
#define DIM     1280
#define D4      (DIM / 4)     // 320 float4 per row
#define CSLICES 320
#define SUBROWS 2
#define NTHREADS (CSLICES * SUBROWS)   // 640
#define BANKS   8
#define EDGE_BLOCKS 32
#define H0_LINES (N_NODES * (DIM * 4) / 128)   // 400000 128B lines
#define W_LINES  (DIM * DIM * 4 / 128)         // 51200 lines per weight matrix

// ---- scratch ----
__device__ float g_outw[N_NODES];
__device__ float g_q[N_NODES];
__device__ float g_Csum;
__device__ float g_S1B[BANKS][DIM];
__device__ float g_msumB[BANKS][DIM];
__device__ float g_v1[DIM];

// ---- software grid barrier ----
__device__ unsigned g_cnt = 0;
__device__ volatile unsigned g_gen = 0;

__device__ __forceinline__ void grid_barrier() {
    __syncthreads();
    if (threadIdx.x == 0) {
        __threadfence();
        unsigned gen = g_gen;
        if (atomicAdd(&g_cnt, 1u) == gridDim.x - 1u) {
            g_cnt = 0;
            __threadfence();
            g_gen = gen + 1u;
        } else {
            while (g_gen == gen) { __nanosleep(64); }
        }
        __threadfence();
    }
    __syncthreads();
}

__device__ __forceinline__ void prefetch_l2(const void* p) {
    asm volatile("prefetch.global.L2 [%0];" :: "l"(p));
}
__device__ __forceinline__ float edge_w(float x) {
    return 1.0f / (x * x + 1e-6f);
}
__device__ __forceinline__ void fma4(float4& a, float c, const float4& v) {
    a.x = fmaf(c, v.x, a.x); a.y = fmaf(c, v.y, a.y);
    a.z = fmaf(c, v.z, a.z); a.w = fmaf(c, v.w, a.w);
}
__device__ __forceinline__ void add4(float4& a, const float4& v) {
    a.x += v.x; a.y += v.y; a.z += v.z; a.w += v.w;
}
__device__ __forceinline__ float dot4(const float4& a, const float4& b) {
    return a.x * b.x + a.y * b.y + a.z * b.z + a.w * b.w;
}

__global__ void __launch_bounds__(NTHREADS, 1)
fused_kernel(const float* __restrict__ node,
             const float* __restrict__ ef,
             const int*   __restrict__ src,
             const int*   __restrict__ dst,
             const float* __restrict__ W1,
             const float* __restrict__ b1,
             const float* __restrict__ W2,
             const float* __restrict__ b2,
             float*       __restrict__ out) {
    const int tid = blockIdx.x * blockDim.x + threadIdx.x;
    const int nt  = gridDim.x * blockDim.x;
    const int lane = threadIdx.x & 31;
    const int warp_in_blk = threadIdx.x >> 5;
    const int idx  = warp_in_blk * gridDim.x + blockIdx.x;
    const int row_mv  = idx >> 1;
    const int half_mv = idx & 1;
    const bool is_edge_blk = (blockIdx.x < EDGE_BLOCKS);

    __shared__ float sh[32];
    __shared__ float s1sh[DIM];
    __shared__ float mssh[DIM];

    // ---------- Phase 1: edge blocks: pass 1 + Csum. others: resets + h0 prefetch ----------
    {
        float csum_local = 0.f;
        if (is_edge_blk) {
            const int et = blockIdx.x * NTHREADS + threadIdx.x;      // 0..20479
            const int estride = EDGE_BLOCKS * NTHREADS;
            for (int e = et; e < N_EDGES; e += estride) {
                float w = edge_w(__ldg(&ef[e]));
                csum_local += w;
                atomicAdd(&g_outw[__ldg(&src[e])], w);
            }
        } else {
            // resets (124 blocks; tiny)
            const int pt = (blockIdx.x - EDGE_BLOCKS) * NTHREADS + threadIdx.x;
            const int pstride = (gridDim.x - EDGE_BLOCKS) * NTHREADS;
            float* s1b = &g_S1B[0][0];
            float* msb = &g_msumB[0][0];
            for (int i = pt; i < BANKS * DIM; i += pstride) { s1b[i] = 0.f; msb[i] = 0.f; }
            for (int i = pt; i < DIM; i += pstride) { g_v1[i] = 0.f; out[i] = 0.f; }
            // full-array L2 prefetch of node features: fire-and-forget stream
            const char* base = (const char*)node;
            for (long l = pt; l < H0_LINES; l += pstride)
                prefetch_l2(base + l * 128);
        }
        // Csum block-reduce (all blocks participate; non-edge contribute 0)
        #pragma unroll
        for (int o = 16; o; o >>= 1)
            csum_local += __shfl_down_sync(0xffffffffu, csum_local, o);
        if (threadIdx.x < 32) sh[threadIdx.x] = 0.f;
        __syncthreads();
        if (lane == 0) sh[warp_in_blk] = csum_local;
        __syncthreads();
        if (threadIdx.x < 32) {
            float v = sh[threadIdx.x];
            #pragma unroll
            for (int o = 16; o; o >>= 1) v += __shfl_down_sync(0xffffffffu, v, o);
            if (threadIdx.x == 0 && is_edge_blk) atomicAdd(&g_Csum, v);
        }
    }
    grid_barrier();

    // ---------- Phase 2: edge blocks: pass 2. others: W1/W2 prefetch ----------
    {
        if (is_edge_blk) {
            const int et = blockIdx.x * NTHREADS + threadIdx.x;
            const int estride = EDGE_BLOCKS * NTHREADS;
            for (int e = et; e < N_EDGES; e += estride) {
                float w = edge_w(__ldg(&ef[e]));
                atomicAdd(&g_q[__ldg(&src[e])], w * (1.0f + g_outw[__ldg(&dst[e])]));
            }
        } else {
            const int pt = (blockIdx.x - EDGE_BLOCKS) * NTHREADS + threadIdx.x;
            const int pstride = (gridDim.x - EDGE_BLOCKS) * NTHREADS;
            const char* w1b = (const char*)W1;
            const char* w2b = (const char*)W2;
            for (long l = pt; l < W_LINES; l += pstride) {
                prefetch_l2(w1b + l * 128);
                prefetch_l2(w2b + l * 128);
            }
        }
    }
    grid_barrier();

    // ---------- Phase 3: column sums, contiguous rows, unroll 8 (R15-proven) ----------
    {
        const int sub = threadIdx.x / CSLICES;                 // 0..1
        const int t   = threadIdx.x - sub * CSLICES;           // 0..319
        const int lo  = (int)(((long)blockIdx.x * N_NODES) / gridDim.x);
        const int hi  = (int)(((long)(blockIdx.x + 1) * N_NODES) / gridDim.x);
        const float4* __restrict__ h4 = (const float4*)node;
        float4 aw = make_float4(0.f, 0.f, 0.f, 0.f);
        float4 as = make_float4(0.f, 0.f, 0.f, 0.f);
        int s = lo + sub;
        for (; s + 14 < hi; s += 16) {
            float c[8]; float4 v[8];
            #pragma unroll
            for (int k = 0; k < 8; k++) {
                int r = s + 2 * k;
                c[k] = 1.0f + __ldg(&g_outw[r]) + __ldg(&g_q[r]);
            }
            #pragma unroll
            for (int k = 0; k < 8; k++) {
                int r = s + 2 * k;
                v[k] = __ldg(&h4[(long)r * D4 + t]);
            }
            #pragma unroll
            for (int k = 0; k < 8; k++) { fma4(aw, c[k], v[k]); add4(as, v[k]); }
        }
        for (; s < hi; s += 2) {
            float c = 1.0f + __ldg(&g_outw[s]) + __ldg(&g_q[s]);
            float4 v = __ldg(&h4[(long)s * D4 + t]);
            fma4(aw, c, v); add4(as, v);
        }
        for (int i = threadIdx.x; i < DIM; i += blockDim.x) { s1sh[i] = 0.f; mssh[i] = 0.f; }
        __syncthreads();
        int d = 4 * t;
        atomicAdd(&s1sh[d + 0], aw.x); atomicAdd(&s1sh[d + 1], aw.y);
        atomicAdd(&s1sh[d + 2], aw.z); atomicAdd(&s1sh[d + 3], aw.w);
        atomicAdd(&mssh[d + 0], as.x); atomicAdd(&mssh[d + 1], as.y);
        atomicAdd(&mssh[d + 2], as.z); atomicAdd(&mssh[d + 3], as.w);
        __syncthreads();
        const int bank = blockIdx.x & (BANKS - 1);
        if (threadIdx.x < CSLICES) {
            float4 v = ((const float4*)s1sh)[threadIdx.x];
            float* dstp = &g_S1B[bank][4 * threadIdx.x];
            atomicAdd(dstp + 0, v.x); atomicAdd(dstp + 1, v.y);
            atomicAdd(dstp + 2, v.z); atomicAdd(dstp + 3, v.w);
        } else {
            int j = threadIdx.x - CSLICES;
            float4 v = ((const float4*)mssh)[j];
            float* dstp = &g_msumB[bank][4 * j];
            atomicAdd(dstp + 0, v.x); atomicAdd(dstp + 1, v.y);
            atomicAdd(dstp + 2, v.z); atomicAdd(dstp + 3, v.w);
        }
    }
    grid_barrier();

    // ---------- Phase 4: bank-sum S1 -> shared, v1 += partial ; reset outw/q ----------
    {
        const float invN = 1.0f / (float)N_NODES;
        const float C = (float)N_NODES + g_Csum;
        for (int i = threadIdx.x; i < DIM; i += blockDim.x) {
            float v = 0.f;
            #pragma unroll
            for (int b = 0; b < BANKS; b++) v += g_S1B[b][i];
            s1sh[i] = v * invN;
        }
        __syncthreads();
        if (row_mv < DIM) {
            const float4* __restrict__ wr = (const float4*)(W1 + (long)row_mv * DIM);
            const float4* __restrict__ s1 = (const float4*)s1sh;
            const int base = half_mv * (D4 / 2) + lane;
            float acc = 0.f;
            #pragma unroll
            for (int k = 0; k < 5; k++) {
                int j = base + k * 32;
                acc += dot4(__ldg(&wr[j]), s1[j]);
            }
            #pragma unroll
            for (int o = 16; o; o >>= 1) acc += __shfl_down_sync(0xffffffffu, acc, o);
            if (lane == 0) {
                float contrib = acc;
                if (half_mv == 0) contrib += C * invN * __ldg(&b1[row_mv]);
                atomicAdd(&g_v1[row_mv], contrib);
            }
        }
        for (int s2 = tid; s2 < N_NODES; s2 += nt) { g_outw[s2] = 0.f; g_q[s2] = 0.f; }
    }
    grid_barrier();

    // ---------- Phase 5: out += partial + b2 + msum/N ; reset Csum ----------
    {
        const float invN = 1.0f / (float)N_NODES;
        if (row_mv < DIM) {
            const float4* __restrict__ wr = (const float4*)(W2 + (long)row_mv * DIM);
            const float4* __restrict__ v1 = (const float4*)g_v1;
            const int base = half_mv * (D4 / 2) + lane;
            float acc = 0.f;
            #pragma unroll
            for (int k = 0; k < 5; k++) {
                int j = base + k * 32;
                acc += dot4(__ldg(&wr[j]), v1[j]);
            }
            #pragma unroll
            for (int o = 16; o; o >>= 1) acc += __shfl_down_sync(0xffffffffu, acc, o);
            if (lane == 0) {
                float contrib = acc;
                if (half_mv == 0) {
                    float ms = 0.f;
                    #pragma unroll
                    for (int b = 0; b < BANKS; b++) ms += g_msumB[b][row_mv];
                    contrib += __ldg(&b2[row_mv]) + ms * invN;
                }
                atomicAdd(&out[row_mv], contrib);
            }
        }
        if (tid == 0) g_Csum = 0.f;
    }
}

extern "C" void kernel_launch(void* const* d_in, const int* in_sizes, int n_in,
                              void* d_out, int out_size) {
    const float* node = (const float*)d_in[0];
    const float* ef   = (const float*)d_in[1];
    const int*   ei   = (const int*)  d_in[2];
    const float* W1   = (const float*)d_in[3];
    const float* b1   = (const float*)d_in[4];
    const float* W2   = (const float*)d_in[5];
    const float* b2   = (const float*)d_in[6];
    float* out = (float*)d_out;

    const int* src = ei;
    const int* dst = ei + N_EDGES;

    int dev = 0, sms = 148, maxb = 1;
    cudaGetDevice(&dev);
    cudaDeviceGetAttribute(&sms, cudaDevAttrMultiProcessorCount, dev);
    cudaOccupancyMaxActiveBlocksPerMultiprocessor(&maxb, fused_kernel, NTHREADS, 0);
    int grid = (maxb >= 1) ? sms : 1;
    if (grid < 1) grid = 1;

    fused_kernel<<<grid, NTHREADS>>>(node, ef, src, dst, W1, b1, W2, b2, out);
}

// round 17
// speedup vs baseline: 1.2135x; 1.2135x over previous
#include <cuda_runtime.h>

#define N_NODES 10000
#define N_EDGES 160000
#define DIM     1280
#define D4      (DIM / 4)     // 320 float4 per row
#define CSLICES 320
#define SUBROWS 2
#define NTHREADS (CSLICES * SUBROWS)   // 640
#define BANKS   8
#define CHUNK_ROWS 16
#define N_CHUNKS (N_NODES / CHUNK_ROWS)   // 625, exact

// ---- scratch ----
__device__ float g_outw[N_NODES];
__device__ float g_q[N_NODES];
__device__ float g_Csum;
__device__ float g_S1B[BANKS][DIM];
__device__ float g_msumB[BANKS][DIM];
__device__ float g_v1[DIM];
__device__ unsigned g_work = 0;        // P3 chunk ticket

// ---- software grid barrier ----
__device__ unsigned g_cnt = 0;
__device__ volatile unsigned g_gen = 0;

__device__ __forceinline__ void grid_barrier() {
    __syncthreads();
    if (threadIdx.x == 0) {
        __threadfence();
        unsigned gen = g_gen;
        if (atomicAdd(&g_cnt, 1u) == gridDim.x - 1u) {
            g_cnt = 0;
            __threadfence();
            g_gen = gen + 1u;
        } else {
            while (g_gen == gen) { __nanosleep(64); }
        }
        __threadfence();
    }
    __syncthreads();
}

__device__ __forceinline__ float edge_w(float x) {
    return 1.0f / (x * x + 1e-6f);
}
__device__ __forceinline__ void fma4(float4& a, float c, const float4& v) {
    a.x = fmaf(c, v.x, a.x); a.y = fmaf(c, v.y, a.y);
    a.z = fmaf(c, v.z, a.z); a.w = fmaf(c, v.w, a.w);
}
__device__ __forceinline__ void add4(float4& a, const float4& v) {
    a.x += v.x; a.y += v.y; a.z += v.z; a.w += v.w;
}
__device__ __forceinline__ float dot4(const float4& a, const float4& b) {
    return a.x * b.x + a.y * b.y + a.z * b.z + a.w * b.w;
}

__global__ void __launch_bounds__(NTHREADS, 1)
fused_kernel(const float* __restrict__ node,
             const float* __restrict__ ef,
             const int*   __restrict__ src,
             const int*   __restrict__ dst,
             const float* __restrict__ W1,
             const float* __restrict__ b1,
             const float* __restrict__ W2,
             const float* __restrict__ b2,
             float*       __restrict__ out) {
    const int tid = blockIdx.x * blockDim.x + threadIdx.x;
    const int nt  = gridDim.x * blockDim.x;
    const int lane = threadIdx.x & 31;
    const int warp_in_blk = threadIdx.x >> 5;
    const int idx  = warp_in_blk * gridDim.x + blockIdx.x;
    const int row_mv  = idx >> 1;
    const int half_mv = idx & 1;

    __shared__ float sh[32];
    __shared__ float s1sh[DIM];
    __shared__ float mssh[DIM];
    __shared__ int   sh_chunk;

    // ---------- Phase 1: edges pass 1 + Csum + resets ----------
    {
        float* s1b = &g_S1B[0][0];
        float* msb = &g_msumB[0][0];
        for (int i = tid; i < BANKS * DIM; i += nt) { s1b[i] = 0.f; msb[i] = 0.f; }
        for (int i = tid; i < DIM; i += nt) { g_v1[i] = 0.f; out[i] = 0.f; }

        float csum_local = 0.f;
        {
            int e0 = tid, e1 = tid + nt;
            float f0 = __ldg(&ef[e0]);
            int   u0 = __ldg(&src[e0]);
            bool has1 = (e1 < N_EDGES);
            float f1 = 0.f; int u1 = 0;
            if (has1) { f1 = __ldg(&ef[e1]); u1 = __ldg(&src[e1]); }
            float w0 = edge_w(f0);
            csum_local += w0;
            atomicAdd(&g_outw[u0], w0);
            if (has1) {
                float w1 = edge_w(f1);
                csum_local += w1;
                atomicAdd(&g_outw[u1], w1);
            }
        }
        #pragma unroll
        for (int o = 16; o; o >>= 1)
            csum_local += __shfl_down_sync(0xffffffffu, csum_local, o);
        if (threadIdx.x < 32) sh[threadIdx.x] = 0.f;
        __syncthreads();
        if (lane == 0) sh[warp_in_blk] = csum_local;
        __syncthreads();
        if (threadIdx.x < 32) {
            float v = sh[threadIdx.x];
            #pragma unroll
            for (int o = 16; o; o >>= 1) v += __shfl_down_sync(0xffffffffu, v, o);
            if (threadIdx.x == 0) atomicAdd(&g_Csum, v);
        }
    }
    grid_barrier();

    // ---------- Phase 2: edges pass 2 ----------
    {
        int e0 = tid, e1 = tid + nt;
        float f0 = __ldg(&ef[e0]);
        int   u0 = __ldg(&src[e0]);
        int   d0 = __ldg(&dst[e0]);
        bool has1 = (e1 < N_EDGES);
        float f1 = 0.f; int u1 = 0, d1 = 0;
        if (has1) { f1 = __ldg(&ef[e1]); u1 = __ldg(&src[e1]); d1 = __ldg(&dst[e1]); }
        float ow0 = g_outw[d0];
        float ow1 = has1 ? g_outw[d1] : 0.f;
        atomicAdd(&g_q[u0], edge_w(f0) * (1.0f + ow0));
        if (has1) atomicAdd(&g_q[u1], edge_w(f1) * (1.0f + ow1));
    }
    grid_barrier();

    // ---------- Phase 3: column sums, dynamic 16-row chunks, unroll 8 ----------
    {
        const int sub = threadIdx.x / CSLICES;                 // 0..1
        const int t   = threadIdx.x - sub * CSLICES;           // 0..319
        const float4* __restrict__ h4 = (const float4*)node;
        float4 aw = make_float4(0.f, 0.f, 0.f, 0.f);
        float4 as = make_float4(0.f, 0.f, 0.f, 0.f);
        for (;;) {
            if (threadIdx.x == 0) sh_chunk = (int)atomicAdd(&g_work, 1u);
            __syncthreads();
            int c = sh_chunk;
            __syncthreads();                                   // protect vs next write
            if (c >= N_CHUNKS) break;
            int s = c * CHUNK_ROWS + sub;                      // 8 rows/thread, step 2
            float cf[8]; float4 v[8];
            #pragma unroll
            for (int k = 0; k < 8; k++) {
                int r = s + 2 * k;
                cf[k] = 1.0f + __ldg(&g_outw[r]) + __ldg(&g_q[r]);
            }
            #pragma unroll
            for (int k = 0; k < 8; k++) {
                int r = s + 2 * k;
                v[k] = __ldg(&h4[(long)r * D4 + t]);
            }
            #pragma unroll
            for (int k = 0; k < 8; k++) { fma4(aw, cf[k], v[k]); add4(as, v[k]); }
        }
        // pairwise block reduction: sub0 stores, sub1 adds (deterministic)
        float4* s1f4 = (float4*)s1sh;
        float4* msf4 = (float4*)mssh;
        if (sub == 0) { s1f4[t] = aw; msf4[t] = as; }
        __syncthreads();
        if (sub == 1) {
            float4 a = s1f4[t]; add4(a, aw); s1f4[t] = a;
            float4 m = msf4[t]; add4(m, as); msf4[t] = m;
        }
        __syncthreads();
        // banked global flush (contention /8)
        const int bank = blockIdx.x & (BANKS - 1);
        if (threadIdx.x < CSLICES) {
            float4 v = s1f4[threadIdx.x];
            float* dstp = &g_S1B[bank][4 * threadIdx.x];
            atomicAdd(dstp + 0, v.x); atomicAdd(dstp + 1, v.y);
            atomicAdd(dstp + 2, v.z); atomicAdd(dstp + 3, v.w);
        } else {
            int j = threadIdx.x - CSLICES;
            float4 v = msf4[j];
            float* dstp = &g_msumB[bank][4 * j];
            atomicAdd(dstp + 0, v.x); atomicAdd(dstp + 1, v.y);
            atomicAdd(dstp + 2, v.z); atomicAdd(dstp + 3, v.w);
        }
    }
    grid_barrier();

    // ---------- Phase 4: bank-sum S1 -> shared, v1 += partial ; resets ----------
    {
        const float invN = 1.0f / (float)N_NODES;
        const float C = (float)N_NODES + g_Csum;
        for (int i = threadIdx.x; i < DIM; i += blockDim.x) {
            float v = 0.f;
            #pragma unroll
            for (int b = 0; b < BANKS; b++) v += g_S1B[b][i];
            s1sh[i] = v * invN;
        }
        __syncthreads();
        if (row_mv < DIM) {
            const float4* __restrict__ wr = (const float4*)(W1 + (long)row_mv * DIM);
            const float4* __restrict__ s1 = (const float4*)s1sh;
            const int base = half_mv * (D4 / 2) + lane;
            float acc = 0.f;
            #pragma unroll
            for (int k = 0; k < 5; k++) {
                int j = base + k * 32;
                acc += dot4(__ldg(&wr[j]), s1[j]);
            }
            #pragma unroll
            for (int o = 16; o; o >>= 1) acc += __shfl_down_sync(0xffffffffu, acc, o);
            if (lane == 0) {
                float contrib = acc;
                if (half_mv == 0) contrib += C * invN * __ldg(&b1[row_mv]);
                atomicAdd(&g_v1[row_mv], contrib);
            }
        }
        for (int s2 = tid; s2 < N_NODES; s2 += nt) { g_outw[s2] = 0.f; g_q[s2] = 0.f; }
        if (tid == 0) g_work = 0;                              // reset ticket
    }
    grid_barrier();

    // ---------- Phase 5: out += partial + b2 + msum/N ; reset Csum ----------
    {
        const float invN = 1.0f / (float)N_NODES;
        if (row_mv < DIM) {
            const float4* __restrict__ wr = (const float4*)(W2 + (long)row_mv * DIM);
            const float4* __restrict__ v1 = (const float4*)g_v1;
            const int base = half_mv * (D4 / 2) + lane;
            float acc = 0.f;
            #pragma unroll
            for (int k = 0; k < 5; k++) {
                int j = base + k * 32;
                acc += dot4(__ldg(&wr[j]), v1[j]);
            }
            #pragma unroll
            for (int o = 16; o; o >>= 1) acc += __shfl_down_sync(0xffffffffu, acc, o);
            if (lane == 0) {
                float contrib = acc;
                if (half_mv == 0) {
                    float ms = 0.f;
                    #pragma unroll
                    for (int b = 0; b < BANKS; b++) ms += g_msumB[b][row_mv];
                    contrib += __ldg(&b2[row_mv]) + ms * invN;
                }
                atomicAdd(&out[row_mv], contrib);
            }
        }
        if (tid == 0) g_Csum = 0.f;
    }
}

extern "C" void kernel_launch(void* const* d_in, const int* in_sizes, int n_in,
                              void* d_out, int out_size) {
    const float* node = (const float*)d_in[0];
    const float* ef   = (const float*)d_in[1];
    const int*   ei   = (const int*)  d_in[2];
    const float* W1   = (const float*)d_in[3];
    const float* b1   = (const float*)d_in[4];
    const float* W2   = (const float*)d_in[5];
    const float* b2   = (const float*)d_in[6];
    float* out = (float*)d_out;

    const int* src = ei;
    const int* dst = ei + N_EDGES;

    int dev = 0, sms = 148, maxb = 1;
    cudaGetDevice(&dev);
    cudaDeviceGetAttribute(&sms, cudaDevAttrMultiProcessorCount, dev);
    cudaOccupancyMaxActiveBlocksPerMultiprocessor(&maxb, fused_kernel, NTHREADS, 0);
    int grid = (maxb >= 1) ? sms : 1;
    if (grid < 1) grid = 1;

    fused_kernel<<<grid, NTHREADS>>>(node, ef, src, dst, W1, b1, W2, b2, out);
}